// round 4
// baseline (speedup 1.0000x reference)
#include <cuda_runtime.h>

#define NN 32
#define CC 64
#define KK 3
#define TT 300
#define VV 25
#define HH 4
#define DD 16
#define CO 64

#define NROWS (NN*TT*VV)          // 240000 rows of (n,t,v)
#define RPT 7500                  // rows per n  (T*V)
#define XPN 480000                // x floats per n (C*T*V)

typedef unsigned long long u64;

__device__ __forceinline__ u64 pk(float x) {
    u64 r; asm("mov.b64 %0, {%1, %1};" : "=l"(r) : "f"(x)); return r;
}
__device__ __forceinline__ u64 pk2(float x, float y) {
    u64 r; asm("mov.b64 %0, {%1, %2};" : "=l"(r) : "f"(x), "f"(y)); return r;
}
__device__ __forceinline__ void fma2(u64& d, u64 a, u64 b) {
    asm("fma.rn.f32x2 %0, %1, %2, %0;" : "+l"(d) : "l"(a), "l"(b));
}
__device__ __forceinline__ float2 up(u64 v) {
    float2 f; asm("mov.b64 {%0, %1}, %2;" : "=f"(f.x), "=f"(f.y) : "l"(v)); return f;
}

// global scratch: activations (q|k|v|conv per row) and attention output
__device__ float g_act[NROWS * 384];   // cols 0-63 q, 64-127 k, 128-191 v, 192-383 conv
__device__ float g_xo[NROWS * 64];

// ===================================================================
// Kernel 1: BN1 + LayerNorm + tall GEMM [240000x64] x [64x384]
// ===================================================================
struct SmemG {
    float s1[CC], b1[CC], lg[CC], lb[CC];
    float cb[192];
    float As[64][68];   // BN1'd rows (fa)
    float Qs[64][68];   // LayerNorm'd rows (qn)
    float Bs[64][388];  // all weights, k-major
};

extern __shared__ float smem_raw[];

__global__ void __launch_bounds__(512) k_gemm(
    const float* __restrict__ x,
    const float* __restrict__ bn1_g, const float* __restrict__ bn1_b,
    const float* __restrict__ bn1_m, const float* __restrict__ bn1_v,
    const float* __restrict__ ln_g,  const float* __restrict__ ln_b,
    const float* __restrict__ wq, const float* __restrict__ wk,
    const float* __restrict__ wv, const float* __restrict__ conv_w,
    const float* __restrict__ conv_b)
{
    SmemG* S = (SmemG*)smem_raw;
    const int tid  = threadIdx.x;
    const int lane = tid & 31;
    const int wid  = tid >> 5;
    const int r0 = blockIdx.x * 64;

    if (tid < CC) {
        float s = bn1_g[tid] * rsqrtf(bn1_v[tid] + 1e-5f);
        S->s1[tid] = s;
        S->b1[tid] = bn1_b[tid] - bn1_m[tid] * s;
        S->lg[tid] = ln_g[tid];
        S->lb[tid] = ln_b[tid];
    }
    if (tid < 192) S->cb[tid] = conv_b[tid];
    // stage weights: Bs[k][col]
    for (int i = tid; i < 64*64; i += 512) {
        int k = i >> 6, c = i & 63;
        S->Bs[k][c]       = wq[i];
        S->Bs[k][64 + c]  = wk[i];
        S->Bs[k][128 + c] = wv[i];
    }
    for (int i = tid; i < 192*64; i += 512) {
        int o = i >> 6, k = i & 63;
        S->Bs[k][192 + o] = conv_w[i];
    }
    __syncthreads();

    // stage A tile: rows r0..r0+63, BN1 applied. row r = n*7500 + t*25 + v
    for (int i = tid; i < 64*64; i += 512) {
        int rr = i & 63;
        int c  = i >> 6;
        int r  = r0 + rr;
        int n  = r / RPT;
        int rem = r - n * RPT;
        S->As[rr][c] = x[n * XPN + c * RPT + rem] * S->s1[c] + S->b1[c];
    }
    __syncthreads();

    // LayerNorm rows -> Qs
    for (int R = wid; R < 64; R += 16) {
        float a0 = S->As[R][lane];
        float a1 = S->As[R][lane + 32];
        float s = a0 + a1;
        #pragma unroll
        for (int o = 16; o; o >>= 1) s += __shfl_xor_sync(0xffffffffu, s, o);
        float mu = s * (1.0f / 64.0f);
        float d0 = a0 - mu, d1 = a1 - mu;
        float ss = d0*d0 + d1*d1;
        #pragma unroll
        for (int o = 16; o; o >>= 1) ss += __shfl_xor_sync(0xffffffffu, ss, o);
        float rstd = rsqrtf(ss * (1.0f / 64.0f) + 1e-6f);
        S->Qs[R][lane]      = d0 * rstd * S->lg[lane]      + S->lb[lane];
        S->Qs[R][lane + 32] = d1 * rstd * S->lg[lane + 32] + S->lb[lane + 32];
    }
    __syncthreads();

    // GEMM: thread = (rg, cg), 4 rows x 12 cols
    const int cg = tid & 31;
    const int rg = tid >> 5;
    const bool useq = (cg < 16);   // g=0 cols 0..63 -> q plane (qn)
    const int c0 = cg * 4;
    const int c1 = 128 + cg * 4;
    const int c2 = 256 + cg * 4;

    u64 acc[4][3][2];
    #pragma unroll
    for (int j = 0; j < 4; ++j) {
        acc[j][0][0] = 0; acc[j][0][1] = 0;
        if (c1 >= 192) {
            acc[j][1][0] = pk2(S->cb[c1-192], S->cb[c1-191]);
            acc[j][1][1] = pk2(S->cb[c1-190], S->cb[c1-189]);
        } else { acc[j][1][0] = 0; acc[j][1][1] = 0; }
        acc[j][2][0] = pk2(S->cb[c2-192], S->cb[c2-191]);
        acc[j][2][1] = pk2(S->cb[c2-190], S->cb[c2-189]);
    }

    const int rbase = rg * 4;
    #pragma unroll 4
    for (int k = 0; k < 64; ++k) {
        u64 pfa[4], pg0[4];
        #pragma unroll
        for (int j = 0; j < 4; ++j) {
            float fa = S->As[rbase + j][k];
            pfa[j] = pk(fa);
            pg0[j] = useq ? pk(S->Qs[rbase + j][k]) : pfa[j];
        }
        float4 b0 = *(const float4*)&S->Bs[k][c0];
        float4 b1 = *(const float4*)&S->Bs[k][c1];
        float4 b2 = *(const float4*)&S->Bs[k][c2];
        u64 b0lo = pk2(b0.x, b0.y), b0hi = pk2(b0.z, b0.w);
        u64 b1lo = pk2(b1.x, b1.y), b1hi = pk2(b1.z, b1.w);
        u64 b2lo = pk2(b2.x, b2.y), b2hi = pk2(b2.z, b2.w);
        #pragma unroll
        for (int j = 0; j < 4; ++j) {
            fma2(acc[j][0][0], pg0[j], b0lo); fma2(acc[j][0][1], pg0[j], b0hi);
            fma2(acc[j][1][0], pfa[j], b1lo); fma2(acc[j][1][1], pfa[j], b1hi);
            fma2(acc[j][2][0], pfa[j], b2lo); fma2(acc[j][2][1], pfa[j], b2hi);
        }
    }

    #pragma unroll
    for (int j = 0; j < 4; ++j) {
        long long r = r0 + rbase + j;
        float* base = g_act + r * 384;
        float2 lo, hi;
        lo = up(acc[j][0][0]); hi = up(acc[j][0][1]);
        *(float4*)(base + c0) = make_float4(lo.x, lo.y, hi.x, hi.y);
        lo = up(acc[j][1][0]); hi = up(acc[j][1][1]);
        *(float4*)(base + c1) = make_float4(lo.x, lo.y, hi.x, hi.y);
        lo = up(acc[j][2][0]); hi = up(acc[j][2][1]);
        *(float4*)(base + c2) = make_float4(lo.x, lo.y, hi.x, hi.y);
    }
}

// ===================================================================
// Kernel 2: per-slice attention (scores + softmax + xo)
// ===================================================================
struct SmemA {
    float Qs[VV][68];
    float Ks[CC][28];
    float Vs[VV][68];
    float attn[HH][VV][28];
};

__global__ void __launch_bounds__(256) k_attn()
{
    SmemA* S = (SmemA*)smem_raw;
    const int tid  = threadIdx.x;
    const int lane = tid & 31;
    const int wid  = tid >> 5;
    const int nt = blockIdx.x;
    const long long rbase = (long long)nt * VV;

    for (int i = tid; i < VV * 192; i += 256) {
        int v = i / 192;
        int e = i - v * 192;
        float val = g_act[(rbase + v) * 384 + e];
        if (e < 64)       S->Qs[v][e] = val;
        else if (e < 128) S->Ks[e - 64][v] = val;
        else              S->Vs[v][e - 128] = val;
    }
    __syncthreads();

    for (int r = wid; r < HH * VV; r += 8) {
        int h  = r / VV;
        int vq = r - h * VV;
        int off = h * DD;
        float sc = -1e30f;
        if (lane < VV) {
            float acc = 0.0f;
            #pragma unroll
            for (int d = 0; d < DD; ++d)
                acc += S->Qs[vq][off + d] * S->Ks[off + d][lane];
            sc = acc * 0.25f;
        }
        float m = sc;
        #pragma unroll
        for (int o = 16; o; o >>= 1) m = fmaxf(m, __shfl_xor_sync(0xffffffffu, m, o));
        float e = (lane < VV) ? __expf(sc - m) : 0.0f;
        float s = e;
        #pragma unroll
        for (int o = 16; o; o >>= 1) s += __shfl_xor_sync(0xffffffffu, s, o);
        if (lane < VV) S->attn[h][vq][lane] = e / s;
    }
    __syncthreads();

    if (tid < VV * 8) {
        int v  = tid >> 3;
        int e8 = (tid & 7) * 8;
        int h  = e8 >> 4;
        u64 a0=0, a1=0, a2=0, a3=0;
        #pragma unroll 5
        for (int w = 0; w < VV; ++w) {
            u64 ap = pk(S->attn[h][v][w]);
            ulonglong2 p0 = *(const ulonglong2*)&S->Vs[w][e8];
            ulonglong2 p1 = *(const ulonglong2*)&S->Vs[w][e8 + 4];
            fma2(a0, ap, p0.x); fma2(a1, ap, p0.y);
            fma2(a2, ap, p1.x); fma2(a3, ap, p1.y);
        }
        float* op = g_xo + (rbase + v) * 64 + e8;
        float2 f0 = up(a0), f1 = up(a1), f2 = up(a2), f3 = up(a3);
        *(float4*)(op)     = make_float4(f0.x, f0.y, f1.x, f1.y);
        *(float4*)(op + 4) = make_float4(f2.x, f2.y, f3.x, f3.y);
    }
}

// ===================================================================
// Kernel 3: per-slice final (fc + residual, graph contraction, merge, BN2, ReLU)
// ===================================================================
struct SmemF {
    float s1[CC], b1[CC], s2[CC], b2[CC];
    float Apad[KK][VV][28];
    float fa_cv[CC][28];
    float fc1[192][28];
    float xoS[28][69];
    float _p[3];
};

__global__ void __launch_bounds__(256) k_final(
    const float* __restrict__ x, const float* __restrict__ Ag,
    const float* __restrict__ bn1_g, const float* __restrict__ bn1_b,
    const float* __restrict__ bn1_m, const float* __restrict__ bn1_v,
    const float* __restrict__ fc_w,  const float* __restrict__ gate_p,
    const float* __restrict__ bn2_g, const float* __restrict__ bn2_b,
    const float* __restrict__ bn2_m, const float* __restrict__ bn2_v,
    float* __restrict__ out)
{
    SmemF* S = (SmemF*)smem_raw;
    const int tid = threadIdx.x;
    const int nt = blockIdx.x;
    const int n  = nt / TT;
    const int t  = nt - n * TT;
    const long long rbase = (long long)nt * VV;

    if (tid < CC) {
        float s = bn1_g[tid] * rsqrtf(bn1_v[tid] + 1e-5f);
        S->s1[tid] = s;
        S->b1[tid] = bn1_b[tid] - bn1_m[tid] * s;
        float s2 = bn2_g[tid] * rsqrtf(bn2_v[tid] + 1e-5f);
        S->s2[tid] = s2;
        S->b2[tid] = bn2_b[tid] - bn2_m[tid] * s2;
    }
    for (int i = tid; i < KK*VV*VV; i += 256) {
        int k = i / (VV*VV);
        int r = i - k * (VV*VV);
        S->Apad[k][r / VV][r % VV] = Ag[i];
    }
    if (tid < 3 * 69) S->xoS[VV + tid / 69][tid % 69] = 0.0f;
    __syncthreads();

    // BN1'd input (residual), c-major
    const float* xp = x + n * XPN + t * VV;
    for (int i = tid; i < CC*VV; i += 256) {
        int c = i / VV;
        int v = i - c * VV;
        S->fa_cv[c][v] = xp[c * RPT + v] * S->s1[c] + S->b1[c];
    }
    // conv activations -> fc1[o][v]
    for (int i = tid; i < VV * 192; i += 256) {
        int v = i / 192;
        int o = i - v * 192;
        S->fc1[o][v] = g_act[(rbase + v) * 384 + 192 + o];
    }
    // xo slice
    for (int i = tid; i < VV * 64; i += 256) {
        int v = i >> 6;
        int e = i & 63;
        S->xoS[v][e] = g_xo[(rbase + v) * 64 + e];
    }
    __syncthreads();

    if (tid < 32 * 7) {
        int cg = tid / 7;
        int wg = tid - cg * 7;
        int c0 = cg * 2;
        int w4 = wg * 4;
        const float gate = __ldg(gate_p);
        // adaptive branch: sum_e xo[w][e] * fc_w[e][c]
        u64 aA00=0, aA01=0, aA10=0, aA11=0;
        #pragma unroll 4
        for (int e = 0; e < CC; ++e) {
            u64 xp0 = pk2(S->xoS[w4+0][e], S->xoS[w4+1][e]);
            u64 xp1 = pk2(S->xoS[w4+2][e], S->xoS[w4+3][e]);
            float2 fw = *(const float2*)(fc_w + e*CC + c0);
            u64 b0 = pk(fw.x), b1 = pk(fw.y);
            fma2(aA00, xp0, b0); fma2(aA01, xp1, b0);
            fma2(aA10, xp0, b1); fma2(aA11, xp1, b1);
        }
        // fixed branch: sum_k sum_v fc1[k*64+c][v] * A[k][v][w]
        u64 aG00=0, aG01=0, aG10=0, aG11=0;
        #pragma unroll
        for (int k = 0; k < KK; ++k) {
            const float* f1a = S->fc1[k*CO + c0];
            const float* f1b = S->fc1[k*CO + c0 + 1];
            #pragma unroll 5
            for (int v = 0; v < VV; ++v) {
                u64 b0 = pk(f1a[v]);
                u64 b1 = pk(f1b[v]);
                ulonglong2 a2 = *(const ulonglong2*)&S->Apad[k][v][w4];
                fma2(aG00, b0, a2.x); fma2(aG01, b0, a2.y);
                fma2(aG10, b1, a2.x); fma2(aG11, b1, a2.y);
            }
        }
        float* op = out + n * XPN + t * VV;
        float fcv[2][4], gcv[2][4];
        float2 f;
        f = up(aA00); fcv[0][0]=f.x; fcv[0][1]=f.y;
        f = up(aA01); fcv[0][2]=f.x; fcv[0][3]=f.y;
        f = up(aA10); fcv[1][0]=f.x; fcv[1][1]=f.y;
        f = up(aA11); fcv[1][2]=f.x; fcv[1][3]=f.y;
        f = up(aG00); gcv[0][0]=f.x; gcv[0][1]=f.y;
        f = up(aG01); gcv[0][2]=f.x; gcv[0][3]=f.y;
        f = up(aG10); gcv[1][0]=f.x; gcv[1][1]=f.y;
        f = up(aG11); gcv[1][2]=f.x; gcv[1][3]=f.y;
        #pragma unroll
        for (int cj = 0; cj < 2; ++cj) {
            int c = c0 + cj;
            float s2 = S->s2[c], b2 = S->b2[c];
            #pragma unroll
            for (int wj = 0; wj < 4; ++wj) {
                int w = w4 + wj;
                if (w < VV) {
                    float fa_tot = fcv[cj][wj] + S->fa_cv[c][w];
                    float fv = (fa_tot * gate + gcv[cj][wj]) * 0.5f;
                    float r = fv * s2 + b2;
                    op[c * RPT + w] = fmaxf(r, 0.0f);
                }
            }
        }
    }
}

extern "C" void kernel_launch(void* const* d_in, const int* in_sizes, int n_in,
                              void* d_out, int out_size)
{
    const float* x      = (const float*)d_in[0];
    const float* A      = (const float*)d_in[1];
    const float* bn1_g  = (const float*)d_in[2];
    const float* bn1_b  = (const float*)d_in[3];
    const float* bn1_m  = (const float*)d_in[4];
    const float* bn1_v  = (const float*)d_in[5];
    const float* conv_w = (const float*)d_in[6];
    const float* conv_b = (const float*)d_in[7];
    const float* ln_g   = (const float*)d_in[8];
    const float* ln_b   = (const float*)d_in[9];
    const float* wq     = (const float*)d_in[10];
    const float* wk     = (const float*)d_in[11];
    const float* wv     = (const float*)d_in[12];
    const float* fc_w   = (const float*)d_in[13];
    const float* gate   = (const float*)d_in[14];
    const float* bn2_g  = (const float*)d_in[15];
    const float* bn2_b  = (const float*)d_in[16];
    const float* bn2_m  = (const float*)d_in[17];
    const float* bn2_v  = (const float*)d_in[18];
    float* out = (float*)d_out;

    static bool attr_done = false;
    if (!attr_done) {
        cudaFuncSetAttribute(k_gemm, cudaFuncAttributeMaxDynamicSharedMemorySize, (int)sizeof(SmemG));
        cudaFuncSetAttribute(k_attn, cudaFuncAttributeMaxDynamicSharedMemorySize, (int)sizeof(SmemA));
        cudaFuncSetAttribute(k_final, cudaFuncAttributeMaxDynamicSharedMemorySize, (int)sizeof(SmemF));
        attr_done = true;
    }

    k_gemm<<<NROWS / 64, 512, sizeof(SmemG)>>>(
        x, bn1_g, bn1_b, bn1_m, bn1_v, ln_g, ln_b, wq, wk, wv, conv_w, conv_b);
    k_attn<<<NN * TT, 256, sizeof(SmemA)>>>();
    k_final<<<NN * TT, 256, sizeof(SmemF)>>>(
        x, A, bn1_g, bn1_b, bn1_m, bn1_v, fc_w, gate,
        bn2_g, bn2_b, bn2_m, bn2_v, out);
}

// round 7
// speedup vs baseline: 1.0094x; 1.0094x over previous
#include <cuda_runtime.h>

#define NN 32
#define CC 64
#define KK 3
#define TT 300
#define VV 25
#define HH 4
#define DD 16
#define CO 64

#define NROWS (NN*TT*VV)          // 240000
#define RPT 7500                  // rows per n  (T*V)
#define XPN 480000                // x floats per n (C*T*V)

typedef unsigned long long u64;

__device__ __forceinline__ u64 pk(float x) {
    u64 r; asm("mov.b64 %0, {%1, %1};" : "=l"(r) : "f"(x)); return r;
}
__device__ __forceinline__ u64 pk2(float x, float y) {
    u64 r; asm("mov.b64 %0, {%1, %2};" : "=l"(r) : "f"(x), "f"(y)); return r;
}
__device__ __forceinline__ void fma2(u64& d, u64 a, u64 b) {
    asm("fma.rn.f32x2 %0, %1, %2, %0;" : "+l"(d) : "l"(a), "l"(b));
}
__device__ __forceinline__ float2 up(u64 v) {
    float2 f; asm("mov.b64 {%0, %1}, %2;" : "=f"(f.x), "=f"(f.y) : "l"(v)); return f;
}

// global scratch: per row (nt,v): cols 0-63 q, 64-127 k, 128-191 v, 192-383 conv
__device__ float g_act[(size_t)NROWS * 384];

extern __shared__ float smem_raw[];

// ===================================================================
// Kernel 1: BN1 (+folded LayerNorm) + tall GEMM [240000x64] x [64x384]
// grid (3750, 2): y=0 -> q|k|v cols, y=1 -> conv cols. 64-row tiles.
// ===================================================================
struct SmemG {
    float s1[CC], b1[CC];
    float Sq[CC], Lq[CC], mu[64], rstd[64];
    float cb[192];
    float As[64][65];     // BN1'd rows
    float Bs[64][196];    // half's weights, k-major (192 cols + pad)
};

__global__ void __launch_bounds__(512, 2) k_gemm(
    const float* __restrict__ x,
    const float* __restrict__ bn1_g, const float* __restrict__ bn1_b,
    const float* __restrict__ bn1_m, const float* __restrict__ bn1_v,
    const float* __restrict__ ln_g,  const float* __restrict__ ln_b,
    const float* __restrict__ wq, const float* __restrict__ wk,
    const float* __restrict__ wv, const float* __restrict__ conv_w,
    const float* __restrict__ conv_b)
{
    SmemG* S = (SmemG*)smem_raw;
    const int tid  = threadIdx.x;
    const int lane = tid & 31;
    const int wid  = tid >> 5;
    const int r0   = blockIdx.x * 64;
    const int half = blockIdx.y;

    // ---- phase A: params + weights (+ LN column sums for q) ----
    if (tid < CC) {
        float s = bn1_g[tid] * rsqrtf(bn1_v[tid] + 1e-5f);
        S->s1[tid] = s;
        S->b1[tid] = bn1_b[tid] - bn1_m[tid] * s;
    }
    if (half == 0) {
        for (int i = tid; i < 64*64; i += 512) {
            int k = i >> 6, c = i & 63;
            S->Bs[k][c]       = ln_g[k] * wq[i];   // lg folded into Wq
            S->Bs[k][64 + c]  = wk[i];
            S->Bs[k][128 + c] = wv[i];
        }
        if (tid < 64) {
            float sq = 0.0f, lq = 0.0f;
            #pragma unroll 4
            for (int k = 0; k < 64; ++k) {
                float w = wq[k*64 + tid];
                sq += ln_g[k] * w;
                lq += ln_b[k] * w;
            }
            S->Sq[tid] = sq;
            S->Lq[tid] = lq;
        }
    } else {
        for (int i = tid; i < 192*64; i += 512) {
            int o = i >> 6, k = i & 63;
            S->Bs[k][o] = conv_w[i];
        }
        if (tid < 192) S->cb[tid] = conv_b[tid];
    }
    __syncthreads();

    // ---- phase B: stage A tile (BN1 applied) ----
    for (int i = tid; i < 64*64; i += 512) {
        int rr = i & 63;
        int c  = i >> 6;
        int r  = r0 + rr;
        int n  = r / RPT;
        int rem = r - n * RPT;
        S->As[rr][c] = x[(size_t)n * XPN + c * RPT + rem] * S->s1[c] + S->b1[c];
    }
    __syncthreads();

    // ---- phase C: LN row stats (half 0 only) ----
    if (half == 0) {
        for (int R = wid; R < 64; R += 16) {
            float a0 = S->As[R][lane];
            float a1 = S->As[R][lane + 32];
            float s = a0 + a1;
            #pragma unroll
            for (int o = 16; o; o >>= 1) s += __shfl_xor_sync(0xffffffffu, s, o);
            float m = s * (1.0f / 64.0f);
            float d0 = a0 - m, d1 = a1 - m;
            float ss = d0*d0 + d1*d1;
            #pragma unroll
            for (int o = 16; o; o >>= 1) ss += __shfl_xor_sync(0xffffffffu, ss, o);
            if (lane == 0) {
                S->mu[R]   = m;
                S->rstd[R] = rsqrtf(ss * (1.0f / 64.0f) + 1e-6f);
            }
        }
    }
    __syncthreads();

    // ---- phase D: GEMM. warp = 12-col group (broadcast B); rows lane & lane+32 ----
    const int c0 = wid * 12;
    u64 acc[2][6];
    if (half == 0) {
        #pragma unroll
        for (int p = 0; p < 6; ++p) { acc[0][p] = 0; acc[1][p] = 0; }
    } else {
        #pragma unroll
        for (int p = 0; p < 6; ++p) {
            u64 bias = pk2(S->cb[c0 + 2*p], S->cb[c0 + 2*p + 1]);
            acc[0][p] = bias; acc[1][p] = bias;
        }
    }

    #pragma unroll 2
    for (int k = 0; k < 64; ++k) {
        u64 aA = pk(S->As[lane][k]);
        u64 aB = pk(S->As[lane + 32][k]);
        {
            float4 b = *(const float4*)&S->Bs[k][c0];
            u64 p0 = pk2(b.x, b.y), p1 = pk2(b.z, b.w);
            fma2(acc[0][0], aA, p0); fma2(acc[1][0], aB, p0);
            fma2(acc[0][1], aA, p1); fma2(acc[1][1], aB, p1);
        }
        {
            float4 b = *(const float4*)&S->Bs[k][c0 + 4];
            u64 p0 = pk2(b.x, b.y), p1 = pk2(b.z, b.w);
            fma2(acc[0][2], aA, p0); fma2(acc[1][2], aB, p0);
            fma2(acc[0][3], aA, p1); fma2(acc[1][3], aB, p1);
        }
        {
            float4 b = *(const float4*)&S->Bs[k][c0 + 8];
            u64 p0 = pk2(b.x, b.y), p1 = pk2(b.z, b.w);
            fma2(acc[0][4], aA, p0); fma2(acc[1][4], aB, p0);
            fma2(acc[0][5], aA, p1); fma2(acc[1][5], aB, p1);
        }
    }

    // ---- epilogue ----
    float muA = 0.f, rsA = 0.f, muB = 0.f, rsB = 0.f;
    if (half == 0) {
        muA = S->mu[lane];      rsA = S->rstd[lane];
        muB = S->mu[lane + 32]; rsB = S->rstd[lane + 32];
    }
    float vA[12], vB[12];
    #pragma unroll
    for (int p = 0; p < 6; ++p) {
        float2 fA = up(acc[0][p]);
        float2 fB = up(acc[1][p]);
        int col0 = c0 + 2*p;
        if (half == 0 && col0 < 64) {        // q-plane: apply folded LN transform
            fA.x = rsA * (fA.x - muA * S->Sq[col0])   + S->Lq[col0];
            fB.x = rsB * (fB.x - muB * S->Sq[col0])   + S->Lq[col0];
            fA.y = rsA * (fA.y - muA * S->Sq[col0+1]) + S->Lq[col0+1];
            fB.y = rsB * (fB.y - muB * S->Sq[col0+1]) + S->Lq[col0+1];
        }
        vA[2*p] = fA.x; vA[2*p+1] = fA.y;
        vB[2*p] = fB.x; vB[2*p+1] = fB.y;
    }
    float* baseA = g_act + (size_t)(r0 + lane)      * 384 + half * 192 + c0;
    float* baseB = g_act + (size_t)(r0 + lane + 32) * 384 + half * 192 + c0;
    #pragma unroll
    for (int q = 0; q < 3; ++q) {
        *(float4*)(baseA + 4*q) = make_float4(vA[4*q], vA[4*q+1], vA[4*q+2], vA[4*q+3]);
        *(float4*)(baseB + 4*q) = make_float4(vB[4*q], vB[4*q+1], vB[4*q+2], vB[4*q+3]);
    }
}

// ===================================================================
// Kernel 2 (fused): attention + fc + residual + graph + merge + BN2 + ReLU
// one block per (n,t)
// ===================================================================
struct SmemF {
    float s2[CC], b2[CC];          // 128 floats
    float Apad[KK][VV][28];        // 2100
    float fa_cv[CC][28];           // 1792
    float xoS[28][69];             // 1932  (sum = 5952 floats -> union base 16B aligned)
    union {
        struct { float Qs[VV][68]; float KsT[CC][28]; float Vs[VV][68]; float attn[HH][VV][28]; } a;
        float fc1[192][28];
    } u;
};

__global__ void __launch_bounds__(256) k_fuse(
    const float* __restrict__ x, const float* __restrict__ Ag,
    const float* __restrict__ bn1_g, const float* __restrict__ bn1_b,
    const float* __restrict__ bn1_m, const float* __restrict__ bn1_v,
    const float* __restrict__ fc_w,  const float* __restrict__ gate_p,
    const float* __restrict__ bn2_g, const float* __restrict__ bn2_b,
    const float* __restrict__ bn2_m, const float* __restrict__ bn2_v,
    float* __restrict__ out)
{
    SmemF* S = (SmemF*)smem_raw;
    const int tid  = threadIdx.x;
    const int lane = tid & 31;
    const int wid  = tid >> 5;
    const int nt = blockIdx.x;
    const int n  = nt / TT;
    const int t  = nt - n * TT;
    const size_t rbase = (size_t)nt * VV;

    // ---- phase 1: stage everything independent ----
    if (tid < CC) {
        float s2 = bn2_g[tid] * rsqrtf(bn2_v[tid] + 1e-5f);
        S->s2[tid] = s2;
        S->b2[tid] = bn2_b[tid] - bn2_m[tid] * s2;
    }
    for (int i = tid; i < KK*VV*VV; i += 256) {
        int k = i / (VV*VV);
        int r = i - k * (VV*VV);
        S->Apad[k][r / VV][r % VV] = Ag[i];
    }
    if (tid < 3 * 69) S->xoS[VV + tid / 69][tid % 69] = 0.0f;
    // attention inputs from g_act
    for (int i = tid; i < VV * 192; i += 256) {
        int v = i / 192;
        int e = i - v * 192;
        float val = g_act[(rbase + v) * 384 + e];
        if (e < 64)       S->u.a.Qs[v][e] = val;
        else if (e < 128) S->u.a.KsT[e - 64][v] = val;
        else              S->u.a.Vs[v][e - 128] = val;
    }
    // residual (BN1'd x), c-major; compute BN params inline
    {
        const float* xp = x + (size_t)n * XPN + t * VV;
        for (int i = tid; i < CC*VV; i += 256) {
            int c = i / VV;
            int v = i - c * VV;
            float s1 = bn1_g[c] * rsqrtf(bn1_v[c] + 1e-5f);
            float b1 = bn1_b[c] - bn1_m[c] * s1;
            S->fa_cv[c][v] = xp[c * RPT + v] * s1 + b1;
        }
    }
    __syncthreads();

    // ---- phase 2: scores + softmax ----
    for (int r = wid; r < HH * VV; r += 8) {
        int h  = r / VV;
        int vq = r - h * VV;
        int off = h * DD;
        float sc = -1e30f;
        if (lane < VV) {
            float acc = 0.0f;
            #pragma unroll
            for (int d = 0; d < DD; ++d)
                acc += S->u.a.Qs[vq][off + d] * S->u.a.KsT[off + d][lane];
            sc = acc * 0.25f;
        }
        float m = sc;
        #pragma unroll
        for (int o = 16; o; o >>= 1) m = fmaxf(m, __shfl_xor_sync(0xffffffffu, m, o));
        float e = (lane < VV) ? __expf(sc - m) : 0.0f;
        float s = e;
        #pragma unroll
        for (int o = 16; o; o >>= 1) s += __shfl_xor_sync(0xffffffffu, s, o);
        if (lane < VV) S->u.a.attn[h][vq][lane] = e / s;
    }
    __syncthreads();

    // ---- phase 3: xo = attn @ V ----
    if (tid < VV * 8) {
        int v  = tid >> 3;
        int e8 = (tid & 7) * 8;
        int h  = e8 >> 4;
        u64 a0=0, a1=0, a2=0, a3=0;
        #pragma unroll 5
        for (int w = 0; w < VV; ++w) {
            u64 ap = pk(S->u.a.attn[h][v][w]);
            ulonglong2 p0 = *(const ulonglong2*)&S->u.a.Vs[w][e8];
            ulonglong2 p1 = *(const ulonglong2*)&S->u.a.Vs[w][e8 + 4];
            fma2(a0, ap, p0.x); fma2(a1, ap, p0.y);
            fma2(a2, ap, p1.x); fma2(a3, ap, p1.y);
        }
        float2 f;
        f = up(a0); S->xoS[v][e8+0] = f.x; S->xoS[v][e8+1] = f.y;
        f = up(a1); S->xoS[v][e8+2] = f.x; S->xoS[v][e8+3] = f.y;
        f = up(a2); S->xoS[v][e8+4] = f.x; S->xoS[v][e8+5] = f.y;
        f = up(a3); S->xoS[v][e8+6] = f.x; S->xoS[v][e8+7] = f.y;
    }
    __syncthreads();   // attn inputs dead -> union becomes fc1

    // ---- phase 4: stage conv activations ----
    for (int i = tid; i < VV * 192; i += 256) {
        int v = i / 192;
        int o = i - v * 192;
        S->u.fc1[o][v] = g_act[(rbase + v) * 384 + 192 + o];
    }
    __syncthreads();

    // ---- phase 5: final tile (2c x 4w) ----
    if (tid < 32 * 7) {
        int cg = tid / 7;
        int wg = tid - cg * 7;
        int c0 = cg * 2;
        int w4 = wg * 4;
        const float gate = __ldg(gate_p);
        // adaptive branch: sum_e xo[w][e] * fc_w[e][c]
        u64 aA00=0, aA01=0, aA10=0, aA11=0;
        #pragma unroll 4
        for (int e = 0; e < CC; ++e) {
            u64 xp0 = pk2(S->xoS[w4+0][e], S->xoS[w4+1][e]);
            u64 xp1 = pk2(S->xoS[w4+2][e], S->xoS[w4+3][e]);
            float2 fw = *(const float2*)(fc_w + e*CC + c0);
            u64 b0 = pk(fw.x), b1 = pk(fw.y);
            fma2(aA00, xp0, b0); fma2(aA01, xp1, b0);
            fma2(aA10, xp0, b1); fma2(aA11, xp1, b1);
        }
        // fixed branch: sum_k sum_v fc1[k*64+c][v] * A[k][v][w]
        u64 aG00=0, aG01=0, aG10=0, aG11=0;
        #pragma unroll
        for (int k = 0; k < KK; ++k) {
            const float* f1a = S->u.fc1[k*CO + c0];
            const float* f1b = S->u.fc1[k*CO + c0 + 1];
            #pragma unroll 5
            for (int v = 0; v < VV; ++v) {
                u64 b0 = pk(f1a[v]);
                u64 b1 = pk(f1b[v]);
                ulonglong2 a2 = *(const ulonglong2*)&S->Apad[k][v][w4];
                fma2(aG00, b0, a2.x); fma2(aG01, b0, a2.y);
                fma2(aG10, b1, a2.x); fma2(aG11, b1, a2.y);
            }
        }
        float* op = out + (size_t)n * XPN + t * VV;
        float fcv[2][4], gcv[2][4];
        float2 f;
        f = up(aA00); fcv[0][0]=f.x; fcv[0][1]=f.y;
        f = up(aA01); fcv[0][2]=f.x; fcv[0][3]=f.y;
        f = up(aA10); fcv[1][0]=f.x; fcv[1][1]=f.y;
        f = up(aA11); fcv[1][2]=f.x; fcv[1][3]=f.y;
        f = up(aG00); gcv[0][0]=f.x; gcv[0][1]=f.y;
        f = up(aG01); gcv[0][2]=f.x; gcv[0][3]=f.y;
        f = up(aG10); gcv[1][0]=f.x; gcv[1][1]=f.y;
        f = up(aG11); gcv[1][2]=f.x; gcv[1][3]=f.y;
        #pragma unroll
        for (int cj = 0; cj < 2; ++cj) {
            int c = c0 + cj;
            float s2 = S->s2[c], b2 = S->b2[c];
            #pragma unroll
            for (int wj = 0; wj < 4; ++wj) {
                int w = w4 + wj;
                if (w < VV) {
                    float fa_tot = fcv[cj][wj] + S->fa_cv[c][w];
                    float fv = (fa_tot * gate + gcv[cj][wj]) * 0.5f;
                    float r = fv * s2 + b2;
                    op[c * RPT + w] = fmaxf(r, 0.0f);
                }
            }
        }
    }
}

extern "C" void kernel_launch(void* const* d_in, const int* in_sizes, int n_in,
                              void* d_out, int out_size)
{
    const float* x      = (const float*)d_in[0];
    const float* A      = (const float*)d_in[1];
    const float* bn1_g  = (const float*)d_in[2];
    const float* bn1_b  = (const float*)d_in[3];
    const float* bn1_m  = (const float*)d_in[4];
    const float* bn1_v  = (const float*)d_in[5];
    const float* conv_w = (const float*)d_in[6];
    const float* conv_b = (const float*)d_in[7];
    const float* ln_g   = (const float*)d_in[8];
    const float* ln_b   = (const float*)d_in[9];
    const float* wq     = (const float*)d_in[10];
    const float* wk     = (const float*)d_in[11];
    const float* wv     = (const float*)d_in[12];
    const float* fc_w   = (const float*)d_in[13];
    const float* gate   = (const float*)d_in[14];
    const float* bn2_g  = (const float*)d_in[15];
    const float* bn2_b  = (const float*)d_in[16];
    const float* bn2_m  = (const float*)d_in[17];
    const float* bn2_v  = (const float*)d_in[18];
    float* out = (float*)d_out;

    cudaFuncSetAttribute(k_gemm, cudaFuncAttributeMaxDynamicSharedMemorySize, (int)sizeof(SmemG));
    cudaFuncSetAttribute(k_fuse, cudaFuncAttributeMaxDynamicSharedMemorySize, (int)sizeof(SmemF));

    dim3 ggrid(NROWS / 64, 2);
    k_gemm<<<ggrid, 512, sizeof(SmemG)>>>(
        x, bn1_g, bn1_b, bn1_m, bn1_v, ln_g, ln_b, wq, wk, wv, conv_w, conv_b);
    k_fuse<<<NN * TT, 256, sizeof(SmemF)>>>(
        x, A, bn1_g, bn1_b, bn1_m, bn1_v, fc_w, gate,
        bn2_g, bn2_b, bn2_m, bn2_v, out);
}